// round 1
// baseline (speedup 1.0000x reference)
#include <cuda_runtime.h>
#include <math.h>

// Problem constants
#define B_ 32
#define C_ 256
#define H_ 56
#define W_ 56
#define HW_ (H_*W_)          // 3136
#define R_ 16
#define HW4_ (HW_/4)         // 784
#define NELEM (B_*C_*HW_)    // 25690112
#define NELEM4 (NELEM/4)     // 6422528

// Scratch (no allocation allowed in kernel_launch)
__device__ float g_avg[B_*C_];
__device__ float g_max[B_*C_];
__device__ float g_ca [B_*C_];
__device__ float g_pooled[B_*2*HW_];
__device__ float g_sa [B_*HW_];

// ---------------------------------------------------------------------------
// Kernel 1: per-(b,c) spatial mean & max. One block per (b,c) plane.
// ---------------------------------------------------------------------------
__global__ __launch_bounds__(256) void k_spatial_pool(const float* __restrict__ x) {
    const int bc = blockIdx.x;                 // 0..8191
    const float4* __restrict__ xp = (const float4*)(x + (size_t)bc * HW_);
    float s = 0.f, m = -INFINITY;
    #pragma unroll 4
    for (int i = threadIdx.x; i < HW4_; i += 256) {
        float4 v = xp[i];
        s += (v.x + v.y) + (v.z + v.w);
        m = fmaxf(m, fmaxf(fmaxf(v.x, v.y), fmaxf(v.z, v.w)));
    }
    // warp reduce
    #pragma unroll
    for (int o = 16; o > 0; o >>= 1) {
        s += __shfl_xor_sync(0xffffffffu, s, o);
        m = fmaxf(m, __shfl_xor_sync(0xffffffffu, m, o));
    }
    __shared__ float ss[8], sm[8];
    const int w = threadIdx.x >> 5, l = threadIdx.x & 31;
    if (l == 0) { ss[w] = s; sm[w] = m; }
    __syncthreads();
    if (threadIdx.x == 0) {
        float S = ss[0], M = sm[0];
        #pragma unroll
        for (int i = 1; i < 8; i++) { S += ss[i]; M = fmaxf(M, sm[i]); }
        g_avg[bc] = S * (1.0f / HW_);
        g_max[bc] = M;
    }
}

// ---------------------------------------------------------------------------
// Kernel 2: channel-attention MLP. One block (256 thr) per batch.
// ca = sigmoid( w2 @ (relu(w1@avg) + relu(w1@max)) )
// ---------------------------------------------------------------------------
__global__ __launch_bounds__(256) void k_mlp(const float* __restrict__ w1,
                                             const float* __restrict__ w2) {
    const int b = blockIdx.x;
    const int t = threadIdx.x;
    __shared__ float sva[C_], svm[C_], hs[R_];
    sva[t] = g_avg[b * C_ + t];
    svm[t] = g_max[b * C_ + t];
    __syncthreads();
    if (t < R_) {
        float ha = 0.f, hm = 0.f;
        const float* __restrict__ wr = w1 + t * C_;
        #pragma unroll 8
        for (int c = 0; c < C_; c++) {
            ha = fmaf(wr[c], sva[c], ha);
            hm = fmaf(wr[c], svm[c], hm);
        }
        hs[t] = fmaxf(ha, 0.f) + fmaxf(hm, 0.f);
    }
    __syncthreads();
    float o = 0.f;
    const float* __restrict__ w2r = w2 + t * R_;
    #pragma unroll
    for (int r = 0; r < R_; r++) o = fmaf(w2r[r], hs[r], o);
    g_ca[b * C_ + t] = 1.0f / (1.0f + __expf(-o));
}

// ---------------------------------------------------------------------------
// Kernel 3: channel-wise mean & max of xc = x*ca  -> pooled (B, 2, H, W)
// thread = one (b, hw); coalesced across hw, loops channels.
// ---------------------------------------------------------------------------
__global__ __launch_bounds__(256) void k_chan_pool(const float* __restrict__ x) {
    const int b = blockIdx.y;
    const int hw = blockIdx.x * 256 + threadIdx.x;
    __shared__ float sca[C_];
    sca[threadIdx.x] = g_ca[b * C_ + threadIdx.x];
    __syncthreads();
    if (hw >= HW_) return;
    const float* __restrict__ xp = x + (size_t)b * C_ * HW_ + hw;
    float s = 0.f, m = -INFINITY;
    #pragma unroll 8
    for (int c = 0; c < C_; c++) {
        float v = xp[(size_t)c * HW_] * sca[c];
        s += v;
        m = fmaxf(m, v);
    }
    g_pooled[b * 2 * HW_ + hw]       = s * (1.0f / C_);
    g_pooled[b * 2 * HW_ + HW_ + hw] = m;
}

// ---------------------------------------------------------------------------
// Kernel 4: 7x7 conv (2 in -> 1 out, pad 3) + sigmoid -> sa (B, H, W)
// ---------------------------------------------------------------------------
__global__ __launch_bounds__(256) void k_conv7(const float* __restrict__ wsp) {
    __shared__ float w[98];
    if (threadIdx.x < 98) w[threadIdx.x] = wsp[threadIdx.x];
    __syncthreads();
    const int b = blockIdx.y;
    const int hw = blockIdx.x * 256 + threadIdx.x;
    if (hw >= HW_) return;
    const int h = hw / W_, wd = hw - h * W_;
    const float* __restrict__ pa = g_pooled + b * 2 * HW_;
    const float* __restrict__ pm = pa + HW_;
    float acc = 0.f;
    #pragma unroll
    for (int kh = 0; kh < 7; kh++) {
        const int hh = h + kh - 3;
        if (hh < 0 || hh >= H_) continue;
        #pragma unroll
        for (int kw = 0; kw < 7; kw++) {
            const int ww = wd + kw - 3;
            if (ww < 0 || ww >= W_) continue;
            const int p = hh * W_ + ww;
            acc = fmaf(w[kh * 7 + kw],      __ldg(&pa[p]), acc);
            acc = fmaf(w[49 + kh * 7 + kw], __ldg(&pm[p]), acc);
        }
    }
    g_sa[b * HW_ + hw] = 1.0f / (1.0f + __expf(-acc));
}

// ---------------------------------------------------------------------------
// Kernel 5: out = x * (1 + ca[b,c] * sa[b,hw]),  float4 vectorized.
// ---------------------------------------------------------------------------
__global__ __launch_bounds__(256) void k_final(const float* __restrict__ x,
                                               float* __restrict__ out) {
    const int idx = blockIdx.x * 256 + threadIdx.x;   // float4 index
    if (idx >= NELEM4) return;
    const int bc = idx / HW4_;            // (b*C + c)
    const int q  = idx - bc * HW4_;       // float4 offset within plane
    const int b  = bc >> 8;               // C = 256
    const float ca = __ldg(&g_ca[bc]);
    const float4 s = __ldg(((const float4*)(g_sa + b * HW_)) + q);
    const float4 v = ((const float4*)x)[idx];
    float4 o;
    o.x = v.x * fmaf(ca, s.x, 1.0f);
    o.y = v.y * fmaf(ca, s.y, 1.0f);
    o.z = v.z * fmaf(ca, s.z, 1.0f);
    o.w = v.w * fmaf(ca, s.w, 1.0f);
    ((float4*)out)[idx] = o;
}

// ---------------------------------------------------------------------------
extern "C" void kernel_launch(void* const* d_in, const int* in_sizes, int n_in,
                              void* d_out, int out_size) {
    const float* x   = (const float*)d_in[0];
    const float* w1  = (const float*)d_in[1];
    const float* w2  = (const float*)d_in[2];
    const float* wsp = (const float*)d_in[3];
    float* out = (float*)d_out;

    k_spatial_pool<<<B_ * C_, 256>>>(x);
    k_mlp<<<B_, 256>>>(w1, w2);
    dim3 g3((HW_ + 255) / 256, B_);
    k_chan_pool<<<g3, 256>>>(x);
    k_conv7<<<g3, 256>>>(wsp);
    k_final<<<NELEM4 / 256, 256>>>(x, out);
}